// round 1
// baseline (speedup 1.0000x reference)
#include <cuda_runtime.h>

// RVOModule: v_next = v_desire + 0.2 * sum_k normal_k
// Shapes: p_cur/v_cur/v_desire (B,N,2) f32; near_ped_idx (B,N,K) i32;
//         neigh_ped_mask (B,N,K) f32; collision_threshold i32 scalar.
// B=256, N=1024, K=32. Warp-per-pedestrian, lane-per-neighbor.

#define TAU 3.0f
#define FIX 0.2f

__global__ __launch_bounds__(256)
void rvo_kernel(const float2* __restrict__ p_cur,
                const float2* __restrict__ v_cur,
                const float2* __restrict__ v_desire,
                const int*    __restrict__ near_idx,
                const float*  __restrict__ neigh_mask,
                const int*    __restrict__ thr_ptr,
                float2*       __restrict__ out,
                int N, int K, int P)
{
    const int w    = (blockIdx.x * blockDim.x + threadIdx.x) >> 5; // pedestrian id
    const int lane = threadIdx.x & 31;
    if (w >= P) return;

    const int b = w / N;            // batch
    const int base = b * N;

    const float thrF = (float)(*thr_ptr);

    const float2 p  = p_cur[w];
    const float2 vd = v_desire[w];

    float cx = 0.0f, cy = 0.0f;

    // K is 32 here (one lane per neighbor); loop handles K multiples of 32.
    for (int k = lane; k < K; k += 32) {
        const int   j = near_idx[(long long)w * K + k];
        const float m = neigh_mask[(long long)w * K + k];

        const float2 np = p_cur[base + j];
        const float2 nv = v_cur[base + j];

        // masked neighbor state
        const float rpx = p.x  - np.x * m;
        const float rpy = p.y  - np.y * m;
        const float rvx = vd.x - nv.x * m;
        const float rvy = vd.y - nv.y * m;

        const float dpv = rpx * rvx + rpy * rvy;
        const float dvv = rvx * rvx + rvy * rvy + 1e-6f;   // reference: +1e-6
        float t = dpv / (dvv + 1e-6f);                     // reference: second +1e-6
        t = fminf(fmaxf(t, 0.0f), TAU);

        const float dx = rpx + t * rvx;
        const float dy = rpy + t * rvy;
        const float min_dist = sqrtf(dx * dx + dy * dy);

        const bool coll = (min_dist < thrF) && (m != 0.0f);

        // normal = (-rpy, rpx); |normal| = |rel_pos|
        const float den = sqrtf(rpx * rpx + rpy * rpy) + 1e-6f;
        const float inv = coll ? (1.0f / den) : 0.0f;
        cx += -rpy * inv;
        cy +=  rpx * inv;
    }

    // warp reduction over the 32 neighbors
    #pragma unroll
    for (int off = 16; off > 0; off >>= 1) {
        cx += __shfl_xor_sync(0xffffffffu, cx, off);
        cy += __shfl_xor_sync(0xffffffffu, cy, off);
    }

    if (lane == 0) {
        out[w] = make_float2(vd.x + cx * FIX, vd.y + cy * FIX);
    }
}

extern "C" void kernel_launch(void* const* d_in, const int* in_sizes, int n_in,
                              void* d_out, int out_size)
{
    const float2* p_cur    = (const float2*)d_in[0];
    const float2* v_cur    = (const float2*)d_in[1];
    const float2* v_desire = (const float2*)d_in[2];
    const int*    near_idx = (const int*)d_in[3];
    const float*  mask     = (const float*)d_in[4];
    const int*    thr      = (const int*)d_in[5];
    float2*       out      = (float2*)d_out;

    const int P = in_sizes[0] / 2;          // B*N pedestrians
    const int K = in_sizes[3] / P;          // neighbors per pedestrian (32)
    const int N = 1024;                     // pedestrians per batch (fixed shape)

    const int threads = 256;                // 8 warps -> 8 pedestrians per block
    const int warpsPerBlock = threads / 32;
    const int blocks = (P + warpsPerBlock - 1) / warpsPerBlock;

    rvo_kernel<<<blocks, threads>>>(p_cur, v_cur, v_desire, near_idx, mask, thr,
                                    out, N, K, P);
}

// round 2
// speedup vs baseline: 1.7566x; 1.7566x over previous
#include <cuda_runtime.h>

// RVOModule on GB300. v_next = v_desire + 0.2 * sum_k normal_k.
// B=256, N=1024, K=32.
// Strategy: block stages one batch's (p,v) as float4[1024] (16KB) in smem;
// gathers become LDS.128. Warp-per-pedestrian, lane-per-neighbor, each warp
// loops over 16 pedestrians for ILP.

#define TAU 3.0f
#define FIX 0.2f

#define NPED 1024
#define KNEI 32
#define BLOCKS_PER_BATCH 4
#define THREADS 512
#define WARPS (THREADS / 32)                          // 16
#define PEDS_PER_BLOCK (NPED / BLOCKS_PER_BATCH)      // 256
#define PEDS_PER_WARP (PEDS_PER_BLOCK / WARPS)        // 16

__global__ __launch_bounds__(THREADS)
void rvo_kernel(const float2* __restrict__ p_cur,
                const float2* __restrict__ v_cur,
                const float2* __restrict__ v_desire,
                const int*    __restrict__ near_idx,
                const float*  __restrict__ neigh_mask,
                const int*    __restrict__ thr_ptr,
                float2*       __restrict__ out)
{
    __shared__ float4 pv[NPED];   // {p.x, p.y, v.x, v.y} per pedestrian, 16KB

    const int b    = blockIdx.x / BLOCKS_PER_BATCH;   // batch id
    const int sub  = blockIdx.x % BLOCKS_PER_BATCH;   // sub-range within batch
    const int base = b * NPED;

    // Stage this batch's positions+velocities (coalesced float2 reads).
    #pragma unroll
    for (int i = threadIdx.x; i < NPED; i += THREADS) {
        const float2 p = p_cur[base + i];
        const float2 v = v_cur[base + i];
        pv[i] = make_float4(p.x, p.y, v.x, v.y);
    }
    __syncthreads();

    const int warp = threadIdx.x >> 5;
    const int lane = threadIdx.x & 31;
    const float thrF = (float)(*thr_ptr);

    const int n0 = sub * PEDS_PER_BLOCK + warp * PEDS_PER_WARP;

    #pragma unroll 4
    for (int i = 0; i < PEDS_PER_WARP; ++i) {
        const int n = n0 + i;          // pedestrian within batch
        const int g = base + n;        // global pedestrian id

        // own state: p from smem (broadcast LDS), v_desire from global
        // (uniform address -> single wavefront, L1/L2 hit)
        const float4 self = pv[n];
        const float2 vd   = v_desire[g];

        // lane handles neighbor 'lane' (K == 32)
        const long long off = (long long)g * KNEI + lane;
        const int   j = near_idx[off];
        const float m = neigh_mask[off];

        const float4 q = pv[j];        // LDS.128 gather

        const float rpx = self.x - q.x * m;
        const float rpy = self.y - q.y * m;
        const float rvx = vd.x   - q.z * m;
        const float rvy = vd.y   - q.w * m;

        const float dpv = rpx * rvx + rpy * rvy;
        const float dvv = rvx * rvx + rvy * rvy + 1e-6f;   // ref: +1e-6
        float t = dpv / (dvv + 1e-6f);                     // ref: second +1e-6
        t = fminf(fmaxf(t, 0.0f), TAU);

        const float dx = rpx + t * rvx;
        const float dy = rpy + t * rvy;
        const float min_dist = sqrtf(dx * dx + dy * dy);

        const bool coll = (min_dist < thrF) && (m != 0.0f);

        const float den = sqrtf(rpx * rpx + rpy * rpy) + 1e-6f;
        const float inv = coll ? (1.0f / den) : 0.0f;
        float cx = -rpy * inv;
        float cy =  rpx * inv;

        // warp reduction over 32 neighbors
        #pragma unroll
        for (int o = 16; o > 0; o >>= 1) {
            cx += __shfl_xor_sync(0xffffffffu, cx, o);
            cy += __shfl_xor_sync(0xffffffffu, cy, o);
        }

        if (lane == 0) {
            out[g] = make_float2(vd.x + cx * FIX, vd.y + cy * FIX);
        }
    }
}

extern "C" void kernel_launch(void* const* d_in, const int* in_sizes, int n_in,
                              void* d_out, int out_size)
{
    const float2* p_cur    = (const float2*)d_in[0];
    const float2* v_cur    = (const float2*)d_in[1];
    const float2* v_desire = (const float2*)d_in[2];
    const int*    near_idx = (const int*)d_in[3];
    const float*  mask     = (const float*)d_in[4];
    const int*    thr      = (const int*)d_in[5];
    float2*       out      = (float2*)d_out;

    const int P = in_sizes[0] / 2;               // B*N pedestrians
    const int nBatches = P / NPED;               // 256
    const int blocks = nBatches * BLOCKS_PER_BATCH;

    rvo_kernel<<<blocks, THREADS>>>(p_cur, v_cur, v_desire, near_idx, mask, thr, out);
}

// round 3
// speedup vs baseline: 1.8569x; 1.0571x over previous
#include <cuda_runtime.h>

// RVOModule on GB300. v_next = v_desire + 0.2 * sum_k normal_k.
// B=256, N=1024, K=32.
// R3: thread-per-pedestrian (no shuffle reduction), smem-staged batch state,
// 32 independent LDS.128 gathers per thread for MLP.

#define TAU 3.0f
#define FIX 0.2f

#define NPED 1024
#define KNEI 32
#define BLOCKS_PER_BATCH 2
#define THREADS 512                                    // peds per block

__global__ __launch_bounds__(THREADS, 2)
void rvo_kernel(const float2* __restrict__ p_cur,
                const float2* __restrict__ v_cur,
                const float2* __restrict__ v_desire,
                const int*    __restrict__ near_idx,
                const float*  __restrict__ neigh_mask,
                const int*    __restrict__ thr_ptr,
                float2*       __restrict__ out)
{
    __shared__ float4 pv[NPED];   // {p.x, p.y, v.x, v.y}, 16 KB

    const int b    = blockIdx.x / BLOCKS_PER_BATCH;
    const int sub  = blockIdx.x % BLOCKS_PER_BATCH;
    const int base = b * NPED;

    // Stage this batch's positions+velocities (coalesced float2 reads).
    #pragma unroll
    for (int i = threadIdx.x; i < NPED; i += THREADS) {
        const float2 p = p_cur[base + i];
        const float2 v = v_cur[base + i];
        pv[i] = make_float4(p.x, p.y, v.x, v.y);
    }
    __syncthreads();

    const int n = sub * THREADS + threadIdx.x;   // pedestrian within batch
    const int g = base + n;                      // global pedestrian id

    const float thrF = (float)(*thr_ptr);
    const float4 self = pv[n];
    const float2 vd   = v_desire[g];

    // 128B-aligned vector views of this pedestrian's neighbor lists
    const int4*   idx4 = (const int4*)  (near_idx   + (long long)g * KNEI);
    const float4* msk4 = (const float4*)(neigh_mask + (long long)g * KNEI);

    float cx = 0.0f, cy = 0.0f;

    #pragma unroll
    for (int q = 0; q < KNEI / 4; ++q) {
        const int4   j4 = idx4[q];
        const float4 m4 = msk4[q];

        const int   js[4] = { j4.x, j4.y, j4.z, j4.w };
        const float ms[4] = { m4.x, m4.y, m4.z, m4.w };

        #pragma unroll
        for (int u = 0; u < 4; ++u) {
            const float m = ms[u];
            const float4 qv = pv[js[u]];          // LDS.128 gather

            const float rpx = self.x - qv.x * m;
            const float rpy = self.y - qv.y * m;
            const float rvx = vd.x   - qv.z * m;
            const float rvy = vd.y   - qv.w * m;

            const float dpv = rpx * rvx + rpy * rvy;
            const float dvv = rvx * rvx + rvy * rvy + 1e-6f;   // ref: +1e-6
            float t = dpv / (dvv + 1e-6f);                     // ref: second +1e-6
            t = fminf(fmaxf(t, 0.0f), TAU);

            const float dx = rpx + t * rvx;
            const float dy = rpy + t * rvy;
            const float min_dist = sqrtf(dx * dx + dy * dy);

            const bool coll = (min_dist < thrF) && (m != 0.0f);

            const float den = sqrtf(rpx * rpx + rpy * rpy) + 1e-6f;
            const float inv = coll ? (1.0f / den) : 0.0f;
            cx += -rpy * inv;
            cy +=  rpx * inv;
        }
    }

    out[g] = make_float2(vd.x + cx * FIX, vd.y + cy * FIX);
}

extern "C" void kernel_launch(void* const* d_in, const int* in_sizes, int n_in,
                              void* d_out, int out_size)
{
    const float2* p_cur    = (const float2*)d_in[0];
    const float2* v_cur    = (const float2*)d_in[1];
    const float2* v_desire = (const float2*)d_in[2];
    const int*    near_idx = (const int*)d_in[3];
    const float*  mask     = (const float*)d_in[4];
    const int*    thr      = (const int*)d_in[5];
    float2*       out      = (float2*)d_out;

    const int P = in_sizes[0] / 2;               // B*N pedestrians
    const int nBatches = P / NPED;               // 256
    const int blocks = nBatches * BLOCKS_PER_BATCH;

    rvo_kernel<<<blocks, THREADS>>>(p_cur, v_cur, v_desire, near_idx, mask, thr, out);
}